// round 7
// baseline (speedup 1.0000x reference)
#include <cuda_runtime.h>
#include <cuda_bf16.h>
#include <cuda_fp16.h>
#include <cuda_fp8.h>
#include <math.h>
#include <stdint.h>

#define N_NODES 100000
#define NFEAT   256
#define HID     32
#define NCOL    64
#define TILE_M  128
#define NT      782

// smem layout
#define BROW_B   528
#define B_BYTES  (NCOL * BROW_B)           // 33792 (bf16 W_hi, ldmatrix rows)
#define W8HI_OFF B_BYTES                   // 16384 fragment-packed e4m3(W_hi)
#define W8LO_OFF (W8HI_OFF + 16384)        // 16384 fragment-packed e4m3(512*W_lo)
#define BIAS_OFF (W8LO_OFF + 16384)        // 64 f32
#define WLIN_OFF (BIAS_OFF + 256)
#define BLIN_OFF (WLIN_OFF + 128)
#define SMEM_TOTAL (BLIN_OFF + 16)         // ~66.9 KB

// persistent device scratch
__device__ __nv_bfloat16 g_Whi[NCOL * NFEAT];   // logical (permuted) k order
__device__ uint8_t g_W8hi[16384];               // physical k, fragment-packed
__device__ uint8_t g_W8lo[16384];
__device__ float g_bias[NCOL];
__device__ float g_wlin[HID];
__device__ float g_blin;

// logical fragment position p -> physical k within a 16-block (bf16 path)
__device__ __forceinline__ int kperm(int p) {
    return (p < 8) ? (4 * (p >> 1) + (p & 1))
                   : (4 * ((p - 8) >> 1) + 2 + (p & 1));
}

__device__ __forceinline__ float foldW(const float* Wz, const float* Wh, int n, int kp) {
    const float* W = (n < HID) ? Wz : Wh;           // (2,1,288,32) row-major
    int nn = n & (HID - 1);
    return W[kp * HID + nn] + W[288 * HID + kp * HID + nn];
}

__global__ void prep_kernel(const float* __restrict__ Wz, const float* __restrict__ bz,
                            const float* __restrict__ Wh, const float* __restrict__ bh,
                            const float* __restrict__ Wlin, const float* __restrict__ blin)
{
    int idx = blockIdx.x * blockDim.x + threadIdx.x;
    if (idx < NCOL * NFEAT) {
        int n = idx / NFEAT, k = idx % NFEAT;
        // bf16 W_hi at LOGICAL index (value from permuted physical col)
        {
            int kp = (k & ~15) | kperm(k & 15);
            float w = foldW(Wz, Wh, n, kp);
            g_Whi[idx] = __float2bfloat16(w);
        }
        // fp8 arrays at PHYSICAL k, fragment-packed for m16n8k32 B-frags
        {
            float w = foldW(Wz, Wh, n, k);
            float whi = __bfloat162float(__float2bfloat16(w));
            float wlo = (w - whi) * 512.0f;
            int kb = k >> 5, r = k & 31;
            int half = r >> 4, q = (r & 15) >> 2, j = r & 3;
            int lt = (n & 7) * 4 + q;                     // lane within frag
            int off = ((kb * 8) + (n >> 3)) * 256 + lt * 8 + half * 4 + j;
            __nv_fp8_e4m3 vh(whi), vl(wlo);
            g_W8hi[off] = *reinterpret_cast<uint8_t*>(&vh);
            g_W8lo[off] = *reinterpret_cast<uint8_t*>(&vl);
        }
    }
    if (blockIdx.x == 0) {
        int t = threadIdx.x;
        if (t < NCOL) g_bias[t] = (t < HID) ? bz[t] : bh[t - HID];
        if (t < HID)  g_wlin[t] = Wlin[t];
        if (t == 0)   g_blin = blin[0];
    }
}

// ---------- asm helpers ----------
#define MMA(acc, a, b0, b1) \
    asm("mma.sync.aligned.m16n8k16.row.col.f32.bf16.bf16.f32 " \
        "{%0,%1,%2,%3}, {%4,%5,%6,%7}, {%8,%9}, {%0,%1,%2,%3};" \
        : "+f"((acc)[0]), "+f"((acc)[1]), "+f"((acc)[2]), "+f"((acc)[3]) \
        : "r"((a)[0]), "r"((a)[1]), "r"((a)[2]), "r"((a)[3]), "r"(b0), "r"(b1))

#define MMA8(cd, a, b0, b1) \
    asm("mma.sync.aligned.m16n8k32.row.col.f16.e4m3.e4m3.f16 " \
        "{%0,%1}, {%2,%3,%4,%5}, {%6,%7}, {%0,%1};" \
        : "+r"((cd)[0]), "+r"((cd)[1]) \
        : "r"((a)[0]), "r"((a)[1]), "r"((a)[2]), "r"((a)[3]), "r"(b0), "r"(b1))

#define LDM4(r, addr) \
    asm("ldmatrix.sync.aligned.m8n8.x4.shared.b16 {%0,%1,%2,%3}, [%4];" \
        : "=r"((r)[0]), "=r"((r)[1]), "=r"((r)[2]), "=r"((r)[3]) : "r"(addr))

#define LDS64(b0, b1, addr) \
    asm("ld.shared.v2.b32 {%0, %1}, [%2];" : "=r"(b0), "=r"(b1) : "r"(addr))

// bf16 hi pack of (fx,fy) + exact fp32 residuals
#define SPLIT2(fx, fy, h, rx, ry) do { \
    asm("cvt.rn.bf16x2.f32 %0, %1, %2;" : "=r"(h) : "f"(fy), "f"(fx)); \
    rx = (fx) - __uint_as_float((h) << 16); \
    ry = (fy) - __uint_as_float((h) & 0xffff0000u); \
} while (0)

// pack 4 floats -> 4 e4m3 bytes (f0 in byte0)
#define PACK_E4M3(out, f0, f1, f2, f3) \
    asm("{\n\t.reg .b16 t1, t2;\n\t" \
        "cvt.rn.satfinite.e4m3x2.f32 t1, %2, %1;\n\t" \
        "cvt.rn.satfinite.e4m3x2.f32 t2, %4, %3;\n\t" \
        "mov.b32 %0, {t1, t2};\n\t}" \
        : "=r"(out) : "f"(f0), "f"(f1), "f"(f2), "f"(f3))

__device__ __forceinline__ float fast_tanh(float v) {
    return 1.0f - 2.0f / (__expf(2.0f * v) + 1.0f);
}

extern __shared__ __align__(128) char smem[];

__global__ __launch_bounds__(256, 3)
void gcn_hmma_kernel(const float* __restrict__ x, float* __restrict__ out)
{
    const int tid  = threadIdx.x;
    const uint32_t sbase = (uint32_t)__cvta_generic_to_shared(smem);

    // ---- stage bf16 W_hi (padded ldmatrix rows) ----
    {
        const uint2* whi = reinterpret_cast<const uint2*>(g_Whi);
#pragma unroll
        for (int i = 0; i < 16; i++) {
            int idx = tid + i * 256;
            int n = idx >> 6, c = idx & 63;
            *reinterpret_cast<uint2*>(smem + n * BROW_B + c * 8) = whi[idx];
        }
    }
    // ---- stage fp8 arrays (linear copy) ----
    {
        const uint4* shi = reinterpret_cast<const uint4*>(g_W8hi);
        const uint4* slo = reinterpret_cast<const uint4*>(g_W8lo);
#pragma unroll
        for (int i = 0; i < 4; i++) {
            int idx = tid + i * 256;   // 0..1023 uint4
            reinterpret_cast<uint4*>(smem + W8HI_OFF)[idx] = shi[idx];
            reinterpret_cast<uint4*>(smem + W8LO_OFF)[idx] = slo[idx];
        }
    }
    if (tid < NCOL) reinterpret_cast<float*>(smem + BIAS_OFF)[tid] = g_bias[tid];
    if (tid < HID)  reinterpret_cast<float*>(smem + WLIN_OFF)[tid] = g_wlin[tid];
    if (tid == 0)   reinterpret_cast<float*>(smem + BLIN_OFF)[0] = g_blin;
    __syncthreads();

    const int warp = tid >> 5, lane = tid & 31;
    const int g = lane >> 2, t = lane & 3;

    const int nodeBase = blockIdx.x * TILE_M + warp * 16;
    const int r0 = nodeBase + g, r1 = r0 + 8;
    const int cr0 = (r0 < N_NODES) ? r0 : (N_NODES - 1);
    const int cr1 = (r1 < N_NODES) ? r1 : (N_NODES - 1);
    const float4* p0 = reinterpret_cast<const float4*>(x) + (size_t)cr0 * 64 + t;
    const float4* p1 = reinterpret_cast<const float4*>(x) + (size_t)cr1 * 64 + t;

    // ldmatrix lane address for bf16 B
    const int lm_n = ((lane >> 4) & 1) * 8 + (lane & 7);
    const int lm_k = ((lane >> 3) & 1) * 8;
    const uint32_t lmhi = sbase + lm_n * BROW_B + lm_k * 2;
    // fp8 B lane base (perfectly linear: lane*8)
    const uint32_t w8lane = sbase + W8HI_OFF + lane * 8;

    float acc[8][4];
#pragma unroll
    for (int i = 0; i < 8; i++)
#pragma unroll
        for (int j = 0; j < 4; j++) acc[i][j] = 0.0f;
    uint32_t accX[8][2];
#pragma unroll
    for (int i = 0; i < 8; i++) { accX[i][0] = 0u; accX[i][1] = 0u; }

#pragma unroll 2
    for (int ks2 = 0; ks2 < 8; ks2++) {
        float4 v0a = __ldg(p0 + ks2 * 8);
        float4 v1a = __ldg(p1 + ks2 * 8);
        float4 v0b = __ldg(p0 + ks2 * 8 + 4);
        float4 v1b = __ldg(p1 + ks2 * 8 + 4);

        uint32_t alo[4], ahi[4];

        // ---- blk0 (k16 idx 2*ks2): bf16 split + MMAs ----
        {
            uint32_t hxy0, hzw0, hxy1, hzw1;
            float ra0, ra1, ra2, ra3, rb0, rb1, rb2, rb3;
            SPLIT2(v0a.x, v0a.y, hxy0, ra0, ra1);
            SPLIT2(v0a.z, v0a.w, hzw0, ra2, ra3);
            SPLIT2(v1a.x, v1a.y, hxy1, rb0, rb1);
            SPLIT2(v1a.z, v1a.w, hzw1, rb2, rb3);
            PACK_E4M3(alo[0], ra0 * 512.0f, ra1 * 512.0f, ra2 * 512.0f, ra3 * 512.0f);
            PACK_E4M3(alo[1], rb0 * 512.0f, rb1 * 512.0f, rb2 * 512.0f, rb3 * 512.0f);
            PACK_E4M3(ahi[0], v0a.x, v0a.y, v0a.z, v0a.w);
            PACK_E4M3(ahi[1], v1a.x, v1a.y, v1a.z, v1a.w);
            uint32_t aF[4] = {hxy0, hxy1, hzw0, hzw1};
#pragma unroll
            for (int nt2 = 0; nt2 < 4; nt2++) {
                uint32_t bh[4];
                LDM4(bh, lmhi + nt2 * (16 * BROW_B) + (2 * ks2) * 32);
                MMA(acc[2 * nt2],     aF, bh[0], bh[1]);
                MMA(acc[2 * nt2 + 1], aF, bh[2], bh[3]);
            }
        }
        // ---- blk1 (k16 idx 2*ks2+1) ----
        {
            uint32_t hxy0, hzw0, hxy1, hzw1;
            float ra0, ra1, ra2, ra3, rb0, rb1, rb2, rb3;
            SPLIT2(v0b.x, v0b.y, hxy0, ra0, ra1);
            SPLIT2(v0b.z, v0b.w, hzw0, ra2, ra3);
            SPLIT2(v1b.x, v1b.y, hxy1, rb0, rb1);
            SPLIT2(v1b.z, v1b.w, hzw1, rb2, rb3);
            PACK_E4M3(alo[2], ra0 * 512.0f, ra1 * 512.0f, ra2 * 512.0f, ra3 * 512.0f);
            PACK_E4M3(alo[3], rb0 * 512.0f, rb1 * 512.0f, rb2 * 512.0f, rb3 * 512.0f);
            PACK_E4M3(ahi[2], v0b.x, v0b.y, v0b.z, v0b.w);
            PACK_E4M3(ahi[3], v1b.x, v1b.y, v1b.z, v1b.w);
            uint32_t aF[4] = {hxy0, hxy1, hzw0, hzw1};
#pragma unroll
            for (int nt2 = 0; nt2 < 4; nt2++) {
                uint32_t bh[4];
                LDM4(bh, lmhi + nt2 * (16 * BROW_B) + (2 * ks2 + 1) * 32);
                MMA(acc[2 * nt2],     aF, bh[0], bh[1]);
                MMA(acc[2 * nt2 + 1], aF, bh[2], bh[3]);
            }
        }
        // ---- fp8 cross terms: x_lo*W_hi then x_hi*W_lo ----
        {
            uint32_t hib = w8lane + ks2 * 2048;
#pragma unroll
            for (int nt = 0; nt < 8; nt++) {
                uint32_t b0, b1;
                LDS64(b0, b1, hib + nt * 256);
                MMA8(accX[nt], alo, b0, b1);
            }
#pragma unroll
            for (int nt = 0; nt < 8; nt++) {
                uint32_t b0, b1;
                LDS64(b0, b1, hib + 16384 + nt * 256);
                MMA8(accX[nt], ahi, b0, b1);
            }
        }
    }

    // ---- epilogue (register/shuffle) ----
    const float* sBias = reinterpret_cast<const float*>(smem + BIAS_OFF);
    const float* sWlin = reinterpret_cast<const float*>(smem + WLIN_OFF);
    const float  blin  = reinterpret_cast<const float*>(smem + BLIN_OFF)[0];
    const float  inv512 = 1.0f / 512.0f;

#pragma unroll
    for (int row = 0; row < 2; row++) {
        float s = 0.0f;
#pragma unroll
        for (int nt = 0; nt < 4; nt++) {
            uint32_t uz = accX[nt][row], uh = accX[nt + 4][row];
            half2 hz = *reinterpret_cast<half2*>(&uz);
            half2 hh = *reinterpret_cast<half2*>(&uh);
            float2 cz = __half22float2(hz);
            float2 ch = __half22float2(hh);
#pragma unroll
            for (int j = 0; j < 2; j++) {
                int c = nt * 8 + 2 * t + j;
                float zv = acc[nt][row * 2 + j]     + (j ? cz.y : cz.x) * inv512 + sBias[c];
                float hv = acc[nt + 4][row * 2 + j] + (j ? ch.y : ch.x) * inv512 + sBias[HID + c];
                float z  = 1.0f / (1.0f + __expf(-zv));
                float th = fast_tanh(hv);
                float h  = fmaxf((1.0f - z) * th, 0.0f);
                s = fmaf(h, sWlin[c], s);
            }
        }
        s += __shfl_xor_sync(0xffffffffu, s, 1);
        s += __shfl_xor_sync(0xffffffffu, s, 2);
        int node = row ? r1 : r0;
        if (t == 0 && node < N_NODES) out[node] = s + blin;
    }
}

extern "C" void kernel_launch(void* const* d_in, const int* in_sizes, int n_in,
                              void* d_out, int out_size)
{
    const float* x    = (const float*)d_in[0];
    const float* Wz   = (const float*)d_in[3];
    const float* bz   = (const float*)d_in[4];
    const float* Wh   = (const float*)d_in[7];
    const float* bh   = (const float*)d_in[8];
    const float* Wlin = (const float*)d_in[9];
    const float* blin = (const float*)d_in[10];
    float* out = (float*)d_out;

    prep_kernel<<<64, 256>>>(Wz, bz, Wh, bh, Wlin, blin);

    cudaFuncSetAttribute(gcn_hmma_kernel,
                         cudaFuncAttributeMaxDynamicSharedMemorySize, SMEM_TOTAL);
    gcn_hmma_kernel<<<NT, 256, SMEM_TOTAL>>>(x, out);
}

// round 8
// speedup vs baseline: 1.3101x; 1.3101x over previous
#include <cuda_runtime.h>
#include <cuda_bf16.h>
#include <math.h>
#include <stdint.h>

#define N_NODES 100000
#define NFEAT   256
#define HID     32
#define NCOL    64
#define TILE_M  128
#define NT      782          // ceil(100000/128)

// B smem: 64 rows x 264 bf16 (528B padded rows, conflict-free ldmatrix phases)
#define BROW_B   528
#define B_BYTES  (NCOL * BROW_B)     // 33792
#define B_HI_OFF 0
#define B_LO_OFF B_BYTES
#define BIAS_OFF (2 * B_BYTES)             // 64 f32
#define WLIN_OFF (BIAS_OFF + 256)          // 32 f32
#define BLIN_OFF (WLIN_OFF + 128)
#define SMEM_TOTAL (BLIN_OFF + 16)         // ~67.9 KB

// persistent device scratch (prep output; W stored K-PERMUTED within 16-blocks)
__device__ __nv_bfloat16 g_Whi[NCOL * NFEAT];
__device__ __nv_bfloat16 g_Wlo[NCOL * NFEAT];
__device__ float g_bias[NCOL];
__device__ float g_wlin[HID];
__device__ float g_blin;

// logical fragment position p -> physical k within a 16-block, so that lane t's
// float4 at physical cols 4t..4t+3 lands at logical (2t,2t+1,2t+8,2t+9)
__device__ __forceinline__ int kperm(int p) {
    return (p < 8) ? (4 * (p >> 1) + (p & 1))
                   : (4 * ((p - 8) >> 1) + 2 + (p & 1));
}

__global__ void prep_kernel(const float* __restrict__ Wz, const float* __restrict__ bz,
                            const float* __restrict__ Wh, const float* __restrict__ bh,
                            const float* __restrict__ Wlin, const float* __restrict__ blin)
{
    int idx = blockIdx.x * blockDim.x + threadIdx.x;
    if (idx < NCOL * NFEAT) {
        int n = idx / NFEAT, k = idx % NFEAT;               // k = logical position
        int kp = (k & ~15) | kperm(k & 15);                 // physical source col
        const float* W = (n < HID) ? Wz : Wh;               // (2,1,288,32) row-major
        int nn = n & (HID - 1);
        float w = W[kp * HID + nn] + W[288 * HID + kp * HID + nn];
        __nv_bfloat16 hi = __float2bfloat16(w);
        g_Whi[idx] = hi;
        g_Wlo[idx] = __float2bfloat16(w - __bfloat162float(hi));
    }
    if (blockIdx.x == 0) {
        int t = threadIdx.x;
        if (t < NCOL) g_bias[t] = (t < HID) ? bz[t] : bh[t - HID];
        if (t < HID)  g_wlin[t] = Wlin[t];
        if (t == 0)   g_blin = blin[0];
    }
}

// ---------- helpers ----------
#define MMA(acc, a, b0, b1) \
    asm("mma.sync.aligned.m16n8k16.row.col.f32.bf16.bf16.f32 " \
        "{%0,%1,%2,%3}, {%4,%5,%6,%7}, {%8,%9}, {%0,%1,%2,%3};" \
        : "+f"((acc)[0]), "+f"((acc)[1]), "+f"((acc)[2]), "+f"((acc)[3]) \
        : "r"((a)[0]), "r"((a)[1]), "r"((a)[2]), "r"((a)[3]), "r"(b0), "r"(b1))

#define LDM4(r, addr) \
    asm("ldmatrix.sync.aligned.m8n8.x4.shared.b16 {%0,%1,%2,%3}, [%4];" \
        : "=r"((r)[0]), "=r"((r)[1]), "=r"((r)[2]), "=r"((r)[3]) : "r"(addr))

// pack (fx,fy) -> bf16x2 hi (exact round) and bf16x2 of residual
#define CVTHILO2(fx, fy, h, l) do { \
    asm("cvt.rn.bf16x2.f32 %0, %1, %2;" : "=r"(h) : "f"(fy), "f"(fx)); \
    float _rx = (fx) - __uint_as_float((h) << 16); \
    float _ry = (fy) - __uint_as_float((h) & 0xffff0000u); \
    asm("cvt.rn.bf16x2.f32 %0, %1, %2;" : "=r"(l) : "f"(_ry), "f"(_rx)); \
} while (0)

#define PREFETCH_L2(p) asm volatile("prefetch.global.L2 [%0];" :: "l"(p))

__device__ __forceinline__ float fast_tanh(float v) {
    return 1.0f - 2.0f / (__expf(2.0f * v) + 1.0f);
}

extern __shared__ __align__(128) char smem[];

__global__ __launch_bounds__(256, 3)
void gcn_hmma_kernel(const float* __restrict__ x, float* __restrict__ out)
{
    const int tid  = threadIdx.x;
    const uint32_t sbase = (uint32_t)__cvta_generic_to_shared(smem);

    // ---- stage B hi/lo into padded smem rows (8B chunks) ----
    {
        const uint2* whi = reinterpret_cast<const uint2*>(g_Whi);
        const uint2* wlo = reinterpret_cast<const uint2*>(g_Wlo);
#pragma unroll
        for (int i = 0; i < 16; i++) {
            int idx = tid + i * 256;          // 0..4095
            int n = idx >> 6, c = idx & 63;   // 64 chunks of 4 bf16 per row
            *reinterpret_cast<uint2*>(smem + B_HI_OFF + n * BROW_B + c * 8) = whi[idx];
            *reinterpret_cast<uint2*>(smem + B_LO_OFF + n * BROW_B + c * 8) = wlo[idx];
        }
    }
    if (tid < NCOL) reinterpret_cast<float*>(smem + BIAS_OFF)[tid] = g_bias[tid];
    if (tid < HID)  reinterpret_cast<float*>(smem + WLIN_OFF)[tid] = g_wlin[tid];
    if (tid == 0)   reinterpret_cast<float*>(smem + BLIN_OFF)[0] = g_blin;
    __syncthreads();

    const int warp = tid >> 5, lane = tid & 31;
    const int g = lane >> 2, t = lane & 3;

    const int nodeBase = blockIdx.x * TILE_M + warp * 16;
    const int r0 = nodeBase + g, r1 = r0 + 8;
    const int cr0 = (r0 < N_NODES) ? r0 : (N_NODES - 1);
    const int cr1 = (r1 < N_NODES) ? r1 : (N_NODES - 1);
    const float4* p0 = reinterpret_cast<const float4*>(x) + (size_t)cr0 * 64 + t;
    const float4* p1 = reinterpret_cast<const float4*>(x) + (size_t)cr1 * 64 + t;

    // warm the L2 for the first few k-blocks of both rows
    PREFETCH_L2(p0);
    PREFETCH_L2(p1);
    PREFETCH_L2(p0 + 8);
    PREFETCH_L2(p1 + 8);

    // ldmatrix per-lane address (logical layout; matches permuted-stored W)
    const int lm_n = ((lane >> 4) & 1) * 8 + (lane & 7);
    const int lm_k = ((lane >> 3) & 1) * 8;
    const uint32_t lmhi = sbase + lm_n * BROW_B + lm_k * 2;

    float acc[8][4];
#pragma unroll
    for (int i = 0; i < 8; i++)
#pragma unroll
        for (int j = 0; j < 4; j++) acc[i][j] = 0.0f;

#pragma unroll 2
    for (int ks = 0; ks < 16; ks++) {
        // pull k-block ks+4 (256B ahead) into L2; issue-only, no registers
        if (ks < 12) {
            PREFETCH_L2(p0 + (ks + 4) * 4);
            PREFETCH_L2(p1 + (ks + 4) * 4);
        }

        float4 v0 = __ldg(p0 + ks * 4);
        float4 v1 = __ldg(p1 + ks * 4);

        uint32_t ah[4], al[4];
        CVTHILO2(v0.x, v0.y, ah[0], al[0]);
        CVTHILO2(v1.x, v1.y, ah[1], al[1]);
        CVTHILO2(v0.z, v0.w, ah[2], al[2]);
        CVTHILO2(v1.z, v1.w, ah[3], al[3]);

        // keep all hi-B fragments live; three de-clustered passes so that
        // consecutive MMAs on the same accumulator are ~8 issues apart
        uint32_t bh[4][4];
#pragma unroll
        for (int nt2 = 0; nt2 < 4; nt2++)
            LDM4(bh[nt2], lmhi + nt2 * (16 * BROW_B) + ks * 32);

#pragma unroll
        for (int nt2 = 0; nt2 < 4; nt2++) {            // pass 1: hi*hi
            MMA(acc[2 * nt2],     ah, bh[nt2][0], bh[nt2][1]);
            MMA(acc[2 * nt2 + 1], ah, bh[nt2][2], bh[nt2][3]);
        }
#pragma unroll
        for (int nt2 = 0; nt2 < 4; nt2++) {            // pass 2: lo*hi (reuse bh)
            MMA(acc[2 * nt2],     al, bh[nt2][0], bh[nt2][1]);
            MMA(acc[2 * nt2 + 1], al, bh[nt2][2], bh[nt2][3]);
        }
#pragma unroll
        for (int nt2 = 0; nt2 < 4; nt2++) {            // pass 3: hi*lo
            uint32_t bl[4];
            LDM4(bl, lmhi + B_BYTES + nt2 * (16 * BROW_B) + ks * 32);
            MMA(acc[2 * nt2],     ah, bl[0], bl[1]);
            MMA(acc[2 * nt2 + 1], ah, bl[2], bl[3]);
        }
    }

    // ---- epilogue: fully register/shuffle based ----
    const float* sBias = reinterpret_cast<const float*>(smem + BIAS_OFF);
    const float* sWlin = reinterpret_cast<const float*>(smem + WLIN_OFF);
    const float  blin  = reinterpret_cast<const float*>(smem + BLIN_OFF)[0];

#pragma unroll
    for (int row = 0; row < 2; row++) {
        float s = 0.0f;
#pragma unroll
        for (int nt = 0; nt < 4; nt++) {
#pragma unroll
            for (int j = 0; j < 2; j++) {
                int c = nt * 8 + 2 * t + j;
                float zv = acc[nt][row * 2 + j]     + sBias[c];
                float hv = acc[nt + 4][row * 2 + j] + sBias[HID + c];
                float z  = 1.0f / (1.0f + __expf(-zv));
                float th = fast_tanh(hv);
                float h  = fmaxf((1.0f - z) * th, 0.0f);
                s = fmaf(h, sWlin[c], s);
            }
        }
        s += __shfl_xor_sync(0xffffffffu, s, 1);
        s += __shfl_xor_sync(0xffffffffu, s, 2);
        int node = row ? r1 : r0;
        if (t == 0 && node < N_NODES) out[node] = s + blin;
    }
}

extern "C" void kernel_launch(void* const* d_in, const int* in_sizes, int n_in,
                              void* d_out, int out_size)
{
    const float* x    = (const float*)d_in[0];
    const float* Wz   = (const float*)d_in[3];
    const float* bz   = (const float*)d_in[4];
    const float* Wh   = (const float*)d_in[7];
    const float* bh   = (const float*)d_in[8];
    const float* Wlin = (const float*)d_in[9];
    const float* blin = (const float*)d_in[10];
    float* out = (float*)d_out;

    prep_kernel<<<64, 256>>>(Wz, bz, Wh, bh, Wlin, blin);

    cudaFuncSetAttribute(gcn_hmma_kernel,
                         cudaFuncAttributeMaxDynamicSharedMemorySize, SMEM_TOTAL);
    gcn_hmma_kernel<<<NT, 256, SMEM_TOTAL>>>(x, out);
}